// round 9
// baseline (speedup 1.0000x reference)
#include <cuda_runtime.h>
#include <cuda_bf16.h>
#include <cstdint>

// Problem constants
#define Nn   8192
#define Kk   4
#define Bb   16
#define Dd   512
#define Mm   64
#define DP1  513
#define CAP  1024
#define NA   (Nn*Kk)   // 32768 assignments

// Scratch (device globals — no allocation allowed)
__device__ float g_inv[Mm*Bb];            // 1/col-norm per (expert, b)
__device__ int   g_count[Mm];
__device__ int   g_list[Mm*CAP];          // assignment ids grouped by expert
__device__ float g_part[(size_t)NA*Dd];   // per-assignment partial writes (64MB)

typedef unsigned long long ull;

// ---- packed f32x2 helpers (sm_100+ PTX) ----
__device__ __forceinline__ ull pk2(float lo, float hi){
    ull v; asm("mov.b64 %0, {%1,%2};" : "=l"(v) : "f"(lo), "f"(hi)); return v;
}
__device__ __forceinline__ void unpk2(ull v, float& lo, float& hi){
    asm("mov.b64 {%0,%1}, %2;" : "=f"(lo), "=f"(hi) : "l"(v));
}
__device__ __forceinline__ void fma2(ull& d, ull a, ull b){
    asm("fma.rn.f32x2 %0, %1, %2, %0;" : "+l"(d) : "l"(a), "l"(b));
}
__device__ __forceinline__ void add2(ull& d, ull a){
    asm("add.rn.f32x2 %0, %0, %1;" : "+l"(d) : "l"(a));
}

// ---------------------------------------------------------------------------
// Kernel 1: column inverse norms (over all D+1 rows) + reset counters
// ---------------------------------------------------------------------------
__global__ void k_norm(const float* __restrict__ U){
    __shared__ float sm[256];
    const int m = blockIdx.x, t = threadIdx.x;
    const int b = t & 15, r0 = t >> 4;
    const float* Um = U + (size_t)m * DP1 * Bb;
    float s = 0.f;
    for (int d = r0; d < DP1; d += 16){
        float v = Um[d*Bb + b];
        s += v*v;
    }
    sm[t] = s;
    __syncthreads();
    if (t < 16){
        float tot = 0.f;
        #pragma unroll
        for (int i = 0; i < 16; i++) tot += sm[t + 16*i];
        float y = rsqrtf(tot);
        y = y * (1.5f - 0.5f*tot*y*y);   // one Newton step for accuracy
        g_inv[m*Bb + t] = y;
    }
    if (t == 0) g_count[m] = 0;
}

// ---------------------------------------------------------------------------
// Kernel 2: counting scatter of assignments into per-expert lists
// ---------------------------------------------------------------------------
__global__ void k_build(const int* __restrict__ idx){
    int a = blockIdx.x * blockDim.x + threadIdx.x;
    if (a < NA){
        int e = idx[a] & 63;
        int pos = atomicAdd(&g_count[e], 1);
        if (pos < CAP) g_list[e*CAP + pos] = a;
    }
}

// ---------------------------------------------------------------------------
// Kernel 3: writes pass, NO atomics. Thread owns d = 2t, 2t+1 (round-7 reg
// layout). Per match: 16 f32x2 FMAs, one STG.64 to per-assignment scratch.
// h row double-buffered across the match loop.
// ---------------------------------------------------------------------------
#define S1 8
__global__ void __launch_bounds__(256) k_writes(const float* __restrict__ h,
                                                const float* __restrict__ U){
    const int e   = blockIdx.x >> 3;     // /S1
    const int sub = blockIdx.x & (S1-1);
    const int t   = threadIdx.x;
    const int d0  = 2*t;
    const float* Ue = U + (size_t)e * DP1 * Bb;

    // Pre-scaled expert rows for d0, d0+1 packed as f32x2 pairs (16 ull)
    ull u0[8], u1[8];
    #pragma unroll
    for (int p = 0; p < 8; p++){
        float i0 = g_inv[e*Bb + 2*p];
        float i1 = g_inv[e*Bb + 2*p + 1];
        u0[p] = pk2(Ue[(size_t)d0*Bb + 2*p]*i0,       Ue[(size_t)d0*Bb + 2*p + 1]*i1);
        u1[p] = pk2(Ue[(size_t)(d0+1)*Bb + 2*p]*i0,   Ue[(size_t)(d0+1)*Bb + 2*p + 1]*i1);
    }

    int cnt = g_count[e]; if (cnt > CAP) cnt = CAP;
    const int s    = (cnt * sub) / S1;
    const int epos = (cnt * (sub+1)) / S1;
    if (s >= epos) return;

    int a = g_list[e*CAP + s];
    const float4* hp = (const float4*)(h + (size_t)a * Bb);
    float4 A0 = __ldg(hp+0), A1 = __ldg(hp+1), A2 = __ldg(hp+2), A3 = __ldg(hp+3);

    for (int i = s; i < epos; i++){
        // pack current row early, then prefetch next row
        ull hh[8] = { pk2(A0.x,A0.y), pk2(A0.z,A0.w), pk2(A1.x,A1.y), pk2(A1.z,A1.w),
                      pk2(A2.x,A2.y), pk2(A2.z,A2.w), pk2(A3.x,A3.y), pk2(A3.z,A3.w) };
        int an = a;
        if (i + 1 < epos) an = g_list[e*CAP + i + 1];
        const float4* hn = (const float4*)(h + (size_t)an * Bb);
        float4 B0 = __ldg(hn+0), B1 = __ldg(hn+1), B2 = __ldg(hn+2), B3 = __ldg(hn+3);

        ull acc0 = 0ull, acc1 = 0ull;
        #pragma unroll
        for (int p = 0; p < 8; p++){
            fma2(acc0, u0[p], hh[p]);
            fma2(acc1, u1[p], hh[p]);
        }
        float x, y;
        unpk2(acc0, x, y); float r0 = x + y;
        unpk2(acc1, x, y); float r1 = x + y;
        *(float2*)(g_part + (size_t)a * Dd + d0) = make_float2(r0, r1);

        a = an; A0 = B0; A1 = B1; A2 = B2; A3 = B3;
    }
}

// ---------------------------------------------------------------------------
// Kernel 3b: 4:1 reduce of partials into out. 2 independent quads per thread
// (8 outstanding LDG.128).
// ---------------------------------------------------------------------------
__global__ void __launch_bounds__(256) k_reduce(float* __restrict__ out){
    const int half = Nn*Dd/8;                        // 524288 quad-slots per half
    int i1 = blockIdx.x * 256 + threadIdx.x;
    int i2 = i1 + half;
    const int n1 = i1 >> 7, q1 = i1 & 127;
    const int n2 = i2 >> 7, q2 = i2 & 127;
    const float4* p1 = (const float4*)(g_part + (size_t)n1 * 4 * Dd);
    const float4* p2 = (const float4*)(g_part + (size_t)n2 * 4 * Dd);
    float4 a = __ldg(p1 + q1),       b = __ldg(p1 + q1 + 128);
    float4 c = __ldg(p1 + q1 + 256), d = __ldg(p1 + q1 + 384);
    float4 e = __ldg(p2 + q2),       f = __ldg(p2 + q2 + 128);
    float4 g = __ldg(p2 + q2 + 256), k = __ldg(p2 + q2 + 384);
    ((float4*)out)[i1] = make_float4(a.x+b.x+c.x+d.x, a.y+b.y+c.y+d.y,
                                     a.z+b.z+c.z+d.z, a.w+b.w+c.w+d.w);
    ((float4*)out)[i2] = make_float4(e.x+f.x+g.x+k.x, e.y+f.y+g.y+k.y,
                                     e.z+f.z+g.z+k.z, e.w+f.w+g.w+k.w);
}

// ---------------------------------------------------------------------------
// Kernel 4: recon + loss. 2 matches per warp (32 acc regs), occupancy 3
// blocks/SM, register-halving tree reduction (31 ull-shfl vs 160).
// ---------------------------------------------------------------------------
#define S2 8
__global__ void __launch_bounds__(256,3) k_recon(const float* __restrict__ h,
                                                 const float* __restrict__ U,
                                                 const float* __restrict__ w,
                                                 float* __restrict__ loss){
    __shared__ __align__(16) float Us[Dd*20];
    __shared__ float wred[8];
    const int e   = blockIdx.x >> 3;     // /S2
    const int sub = blockIdx.x & (S2-1);
    const float* Ue = U + (size_t)e * DP1 * Bb;

    // cooperative vectorized load + normalize into padded smem
    {
        const float4* Uf = (const float4*)Ue;
        const float4* iv = (const float4*)(g_inv + e*Bb);
        for (int i = threadIdx.x; i < Dd*4; i += 256){
            int d = i >> 2, bq = i & 3;
            float4 u = __ldg(Uf + (size_t)d*4 + bq);
            float4 s4 = iv[bq];
            u.x *= s4.x; u.y *= s4.y; u.z *= s4.z; u.w *= s4.w;
            ((float4*)&Us[d*20])[bq] = u;
        }
    }
    __syncthreads();

    int cnt = g_count[e]; if (cnt > CAP) cnt = CAP;
    const int s    = (cnt * sub) / S2;
    const int epos = (cnt * (sub+1)) / S2;
    const int lane = threadIdx.x & 31;
    const int wid  = threadIdx.x >> 5;

    float lsum = 0.f;

    for (int g0 = s + wid*2; g0 < epos; g0 += 16){
        int g1 = g0 + 1;
        bool v1 = g1 < epos;
        const int a0 = g_list[e*CAP + g0];
        const int a1 = g_list[e*CAP + (v1 ? g1 : g0)];
        const float vm0 = 1.f, vm1 = v1 ? 1.f : 0.f;

        const float* w0 = w + (size_t)(a0 >> 2) * Dd;
        const float* w1 = w + (size_t)(a1 >> 2) * Dd;

        ull r2[16];   // [0..7]=match0 b-pairs, [8..15]=match1
        #pragma unroll
        for (int p = 0; p < 16; p++) r2[p] = 0ull;

        for (int j = 0; j < 16; j++){
            const int d = lane + 32*j;
            float wv0 = __ldg(w0 + d), wv1 = __ldg(w1 + d);
            ull ww0 = pk2(wv0, wv0), ww1 = pk2(wv1, wv1);
            const float4* row = (const float4*)&Us[d*20];
            #pragma unroll
            for (int bq = 0; bq < 4; bq++){
                float4 u = row[bq];
                ull uL = pk2(u.x, u.y), uH = pk2(u.z, u.w);
                fma2(r2[2*bq],     ww0, uL); fma2(r2[2*bq+1],     ww0, uH);
                fma2(r2[8+2*bq],   ww1, uL); fma2(r2[8+2*bq+1],   ww1, uH);
            }
        }

        // register-halving tree reduce: 16 ull/lane -> 1 fully-reduced ull/lane
        {
            const bool h16 = (lane & 16) != 0;
            #pragma unroll
            for (int i = 0; i < 8; i++){
                ull oL = __shfl_xor_sync(0xffffffffu, r2[i],     16);
                ull oH = __shfl_xor_sync(0xffffffffu, r2[i + 8], 16);
                ull x = h16 ? r2[i + 8] : r2[i];
                ull o = h16 ? oH : oL;
                add2(x, o); r2[i] = x;
            }
            const bool h8 = (lane & 8) != 0;
            #pragma unroll
            for (int i = 0; i < 4; i++){
                ull oL = __shfl_xor_sync(0xffffffffu, r2[i],     8);
                ull oH = __shfl_xor_sync(0xffffffffu, r2[i + 4], 8);
                ull x = h8 ? r2[i + 4] : r2[i];
                ull o = h8 ? oH : oL;
                add2(x, o); r2[i] = x;
            }
            const bool h4 = (lane & 4) != 0;
            #pragma unroll
            for (int i = 0; i < 2; i++){
                ull oL = __shfl_xor_sync(0xffffffffu, r2[i],     4);
                ull oH = __shfl_xor_sync(0xffffffffu, r2[i + 2], 4);
                ull x = h4 ? r2[i + 2] : r2[i];
                ull o = h4 ? oH : oL;
                add2(x, o); r2[i] = x;
            }
            const bool h2 = (lane & 2) != 0;
            {
                ull oL = __shfl_xor_sync(0xffffffffu, r2[0], 2);
                ull oH = __shfl_xor_sync(0xffffffffu, r2[1], 2);
                ull x = h2 ? r2[1] : r2[0];
                ull o = h2 ? oH : oL;
                add2(x, o); r2[0] = x;
            }
            ull o1 = __shfl_xor_sync(0xffffffffu, r2[0], 1);
            add2(r2[0], o1);
        }

        // lane holds full sum of (b0, b0+1) for match m; each value on 2 lanes
        const int  m  = (lane >> 4) & 1;
        const int  b0 = lane & 14;
        const int  am = m ? a1 : a0;
        const float vmm = m ? vm1 : vm0;
        float rl, rh; unpk2(r2[0], rl, rh);
        const float* hp = h + (size_t)am * Bb + b0;
        float h0 = __ldg(hp), h1 = __ldg(hp + 1);
        float e0 = rl - h0, e1 = rh - h1;
        float c = (e0*e0 + e1*e1) * vmm * 0.5f;   // 0.5: each value duplicated on 2 lanes
        #pragma unroll
        for (int ofs = 16; ofs > 0; ofs >>= 1)
            c += __shfl_xor_sync(0xffffffffu, c, ofs);
        if (lane == 0) lsum += c;
    }

    if (lane == 0) wred[wid] = lsum;
    __syncthreads();
    if (threadIdx.x == 0){
        float sblk = 0.f;
        #pragma unroll
        for (int i = 0; i < 8; i++) sblk += wred[i];
        atomicAdd(loss, sblk * (1.0f / (float)(Nn*Kk*Bb)));
    }
}

// ---------------------------------------------------------------------------
extern "C" void kernel_launch(void* const* d_in, const int* in_sizes, int n_in,
                              void* d_out, int out_size){
    const float* h   = (const float*)d_in[0];   // (N,K,B) f32
    const int*   idx = (const int*)  d_in[1];   // (N,K) i32
    const float* U   = (const float*)d_in[2];   // (M,D+1,B) f32

    float* out  = (float*)d_out;                // writes (N,D) then loss scalar
    float* loss = out + (out_size - 1);

    cudaMemsetAsync(loss, 0, sizeof(float));    // only the loss scalar needs zeroing
    k_norm  <<<Mm, 256>>>(U);
    k_build <<<NA/256, 256>>>(idx);
    k_writes<<<Mm*S1, 256>>>(h, U);
    k_reduce<<<(Nn*Dd/8)/256, 256>>>(out);      // 2048 blocks, 2 quads/thread
    k_recon <<<Mm*S2, 256>>>(h, U, out, loss);
}

// round 10
// speedup vs baseline: 1.0283x; 1.0283x over previous
#include <cuda_runtime.h>
#include <cuda_bf16.h>
#include <cstdint>

// Problem constants
#define Nn   8192
#define Kk   4
#define Bb   16
#define Dd   512
#define Mm   64
#define DP1  513
#define CAP  1024
#define NA   (Nn*Kk)   // 32768 assignments

// Scratch (device globals — no allocation allowed)
__device__ float g_inv[Mm*Bb];            // 1/col-norm per (expert, b)
__device__ int   g_count[Mm];
__device__ int   g_list[Mm*CAP];          // assignment ids grouped by expert
__device__ float g_part[(size_t)NA*Dd];   // per-assignment partial writes (64MB)

typedef unsigned long long ull;

// ---- packed f32x2 helpers (sm_100+ PTX) ----
__device__ __forceinline__ ull pk2(float lo, float hi){
    ull v; asm("mov.b64 %0, {%1,%2};" : "=l"(v) : "f"(lo), "f"(hi)); return v;
}
__device__ __forceinline__ void unpk2(ull v, float& lo, float& hi){
    asm("mov.b64 {%0,%1}, %2;" : "=f"(lo), "=f"(hi) : "l"(v));
}
__device__ __forceinline__ void fma2(ull& d, ull a, ull b){
    asm("fma.rn.f32x2 %0, %1, %2, %0;" : "+l"(d) : "l"(a), "l"(b));
}
__device__ __forceinline__ void add2(ull& d, ull a){
    asm("add.rn.f32x2 %0, %0, %1;" : "+l"(d) : "l"(a));
}

// ---------------------------------------------------------------------------
// Kernel 1: column inverse norms (over all D+1 rows) + reset counters
// ---------------------------------------------------------------------------
__global__ void k_norm(const float* __restrict__ U){
    __shared__ float sm[256];
    const int m = blockIdx.x, t = threadIdx.x;
    const int b = t & 15, r0 = t >> 4;
    const float* Um = U + (size_t)m * DP1 * Bb;
    float s = 0.f;
    for (int d = r0; d < DP1; d += 16){
        float v = Um[d*Bb + b];
        s += v*v;
    }
    sm[t] = s;
    __syncthreads();
    if (t < 16){
        float tot = 0.f;
        #pragma unroll
        for (int i = 0; i < 16; i++) tot += sm[t + 16*i];
        float y = rsqrtf(tot);
        y = y * (1.5f - 0.5f*tot*y*y);   // one Newton step for accuracy
        g_inv[m*Bb + t] = y;
    }
    if (t == 0) g_count[m] = 0;
}

// ---------------------------------------------------------------------------
// Kernel 2: counting scatter of assignments into per-expert lists
// ---------------------------------------------------------------------------
__global__ void k_build(const int* __restrict__ idx){
    int a = blockIdx.x * blockDim.x + threadIdx.x;
    if (a < NA){
        int e = idx[a] & 63;
        int pos = atomicAdd(&g_count[e], 1);
        if (pos < CAP) g_list[e*CAP + pos] = a;
    }
}

// ---------------------------------------------------------------------------
// Kernel 3: writes pass, NO atomics. Thread owns d = 2t, 2t+1. Per match:
// 16 f32x2 FMAs, one STG.64 to per-assignment scratch. h row double-buffered.
// ---------------------------------------------------------------------------
#define S1 8
__global__ void __launch_bounds__(256) k_writes(const float* __restrict__ h,
                                                const float* __restrict__ U){
    const int e   = blockIdx.x >> 3;     // /S1
    const int sub = blockIdx.x & (S1-1);
    const int t   = threadIdx.x;
    const int d0  = 2*t;
    const float* Ue = U + (size_t)e * DP1 * Bb;

    // Pre-scaled expert rows for d0, d0+1 packed as f32x2 pairs (16 ull)
    ull u0[8], u1[8];
    #pragma unroll
    for (int p = 0; p < 8; p++){
        float i0 = g_inv[e*Bb + 2*p];
        float i1 = g_inv[e*Bb + 2*p + 1];
        u0[p] = pk2(Ue[(size_t)d0*Bb + 2*p]*i0,       Ue[(size_t)d0*Bb + 2*p + 1]*i1);
        u1[p] = pk2(Ue[(size_t)(d0+1)*Bb + 2*p]*i0,   Ue[(size_t)(d0+1)*Bb + 2*p + 1]*i1);
    }

    int cnt = g_count[e]; if (cnt > CAP) cnt = CAP;
    const int s    = (cnt * sub) / S1;
    const int epos = (cnt * (sub+1)) / S1;
    if (s >= epos) return;

    int a = g_list[e*CAP + s];
    const float4* hp = (const float4*)(h + (size_t)a * Bb);
    float4 A0 = __ldg(hp+0), A1 = __ldg(hp+1), A2 = __ldg(hp+2), A3 = __ldg(hp+3);

    for (int i = s; i < epos; i++){
        ull hh[8] = { pk2(A0.x,A0.y), pk2(A0.z,A0.w), pk2(A1.x,A1.y), pk2(A1.z,A1.w),
                      pk2(A2.x,A2.y), pk2(A2.z,A2.w), pk2(A3.x,A3.y), pk2(A3.z,A3.w) };
        int an = a;
        if (i + 1 < epos) an = g_list[e*CAP + i + 1];
        const float4* hn = (const float4*)(h + (size_t)an * Bb);
        float4 B0 = __ldg(hn+0), B1 = __ldg(hn+1), B2 = __ldg(hn+2), B3 = __ldg(hn+3);

        ull acc0 = 0ull, acc1 = 0ull;
        #pragma unroll
        for (int p = 0; p < 8; p++){
            fma2(acc0, u0[p], hh[p]);
            fma2(acc1, u1[p], hh[p]);
        }
        float x, y;
        unpk2(acc0, x, y); float r0 = x + y;
        unpk2(acc1, x, y); float r1 = x + y;
        *(float2*)(g_part + (size_t)a * Dd + d0) = make_float2(r0, r1);

        a = an; A0 = B0; A1 = B1; A2 = B2; A3 = B3;
    }
}

// ---------------------------------------------------------------------------
// Kernel 3b: 4:1 reduce of partials into out. 2 independent quads per thread
// (8 outstanding LDG.128).
// ---------------------------------------------------------------------------
__global__ void __launch_bounds__(256) k_reduce(float* __restrict__ out){
    const int half = Nn*Dd/8;                        // 524288 quad-slots per half
    int i1 = blockIdx.x * 256 + threadIdx.x;
    int i2 = i1 + half;
    const int n1 = i1 >> 7, q1 = i1 & 127;
    const int n2 = i2 >> 7, q2 = i2 & 127;
    const float4* p1 = (const float4*)(g_part + (size_t)n1 * 4 * Dd);
    const float4* p2 = (const float4*)(g_part + (size_t)n2 * 4 * Dd);
    float4 a = __ldg(p1 + q1),       b = __ldg(p1 + q1 + 128);
    float4 c = __ldg(p1 + q1 + 256), d = __ldg(p1 + q1 + 384);
    float4 e = __ldg(p2 + q2),       f = __ldg(p2 + q2 + 128);
    float4 g = __ldg(p2 + q2 + 256), k = __ldg(p2 + q2 + 384);
    ((float4*)out)[i1] = make_float4(a.x+b.x+c.x+d.x, a.y+b.y+c.y+d.y,
                                     a.z+b.z+c.z+d.z, a.w+b.w+c.w+d.w);
    ((float4*)out)[i2] = make_float4(e.x+f.x+g.x+k.x, e.y+f.y+g.y+k.y,
                                     e.z+f.z+g.z+k.z, e.w+f.w+g.w+k.w);
}

// ---------------------------------------------------------------------------
// Kernel 4: recon + loss — PROVEN round-2 version (39us measured), S2=4.
// Un in SMEM (row pad 20 floats -> conflict-free LDS.128), one warp handles
// 4 matches, full butterfly reduce, atomic loss.
// ---------------------------------------------------------------------------
#define S2 4
__global__ void __launch_bounds__(256,2) k_recon(const float* __restrict__ h,
                                                 const float* __restrict__ U,
                                                 const float* __restrict__ w,
                                                 float* __restrict__ loss){
    __shared__ __align__(16) float Us[Dd*20];
    __shared__ float wred[8];
    const int e   = blockIdx.x >> 2;     // /S2
    const int sub = blockIdx.x & (S2-1);
    const float* Ue = U + (size_t)e * DP1 * Bb;

    // cooperative load + normalize into padded smem
    for (int i = threadIdx.x; i < Dd*Bb; i += 256){
        int d = i >> 4, b = i & 15;
        Us[d*20 + b] = Ue[i] * g_inv[e*Bb + b];
    }
    __syncthreads();

    int cnt = g_count[e]; if (cnt > CAP) cnt = CAP;
    const int s    = (cnt * sub) / S2;
    const int epos = (cnt * (sub+1)) / S2;
    const int lane = threadIdx.x & 31;
    const int wid  = threadIdx.x >> 5;

    float lsum = 0.f;

    for (int g0 = s + wid*4; g0 < epos; g0 += 8*4){
        int a_[4]; float vm[4];
        #pragma unroll
        for (int mi = 0; mi < 4; mi++){
            int gi = g0 + mi;
            bool v = gi < epos;
            a_[mi] = g_list[e*CAP + (v ? gi : (epos-1))];
            vm[mi] = v ? 1.f : 0.f;
        }
        const float* w0 = w + (size_t)(a_[0] >> 2) * Dd;
        const float* w1 = w + (size_t)(a_[1] >> 2) * Dd;
        const float* w2 = w + (size_t)(a_[2] >> 2) * Dd;
        const float* w3 = w + (size_t)(a_[3] >> 2) * Dd;

        ull r2[4][8];
        #pragma unroll
        for (int m = 0; m < 4; m++)
            #pragma unroll
            for (int p = 0; p < 8; p++) r2[m][p] = 0ull;

        for (int j = 0; j < 16; j++){
            const int d = lane + 32*j;
            float wv0 = __ldg(w0 + d), wv1 = __ldg(w1 + d);
            float wv2 = __ldg(w2 + d), wv3 = __ldg(w3 + d);
            ull ww0 = pk2(wv0, wv0), ww1 = pk2(wv1, wv1);
            ull ww2 = pk2(wv2, wv2), ww3 = pk2(wv3, wv3);
            const float4* row = (const float4*)&Us[d*20];
            #pragma unroll
            for (int bq = 0; bq < 4; bq++){
                float4 u = row[bq];
                ull uL = pk2(u.x, u.y), uH = pk2(u.z, u.w);
                fma2(r2[0][2*bq], ww0, uL); fma2(r2[0][2*bq+1], ww0, uH);
                fma2(r2[1][2*bq], ww1, uL); fma2(r2[1][2*bq+1], ww1, uH);
                fma2(r2[2][2*bq], ww2, uL); fma2(r2[2][2*bq+1], ww2, uH);
                fma2(r2[3][2*bq], ww3, uL); fma2(r2[3][2*bq+1], ww3, uH);
            }
        }

        // butterfly reduce across the 32 lanes (packed adds)
        #pragma unroll
        for (int ofs = 16; ofs > 0; ofs >>= 1){
            #pragma unroll
            for (int m = 0; m < 4; m++)
                #pragma unroll
                for (int p = 0; p < 8; p++){
                    ull o = __shfl_xor_sync(0xffffffffu, r2[m][p], ofs);
                    add2(r2[m][p], o);
                }
        }

        // loss terms (all lanes compute the same value; lane 0 accumulates)
        float tot = 0.f;
        #pragma unroll
        for (int m = 0; m < 4; m++){
            const float4* hp = (const float4*)(h + (size_t)a_[m] * Bb);
            float4 hq0 = hp[0], hq1 = hp[1], hq2 = hp[2], hq3 = hp[3];
            float hv[16] = { hq0.x,hq0.y,hq0.z,hq0.w, hq1.x,hq1.y,hq1.z,hq1.w,
                             hq2.x,hq2.y,hq2.z,hq2.w, hq3.x,hq3.y,hq3.z,hq3.w };
            float tm = 0.f;
            #pragma unroll
            for (int p = 0; p < 8; p++){
                float rl, rh; unpk2(r2[m][p], rl, rh);
                float d0 = rl - hv[2*p];
                float d1 = rh - hv[2*p+1];
                tm += d0*d0 + d1*d1;
            }
            tot += vm[m] * tm;
        }
        if (lane == 0) lsum += tot;
    }

    if (lane == 0) wred[wid] = lsum;
    __syncthreads();
    if (threadIdx.x == 0){
        float sblk = 0.f;
        #pragma unroll
        for (int i = 0; i < 8; i++) sblk += wred[i];
        atomicAdd(loss, sblk * (1.0f / (float)(Nn*Kk*Bb)));
    }
}

// ---------------------------------------------------------------------------
extern "C" void kernel_launch(void* const* d_in, const int* in_sizes, int n_in,
                              void* d_out, int out_size){
    const float* h   = (const float*)d_in[0];   // (N,K,B) f32
    const int*   idx = (const int*)  d_in[1];   // (N,K) i32
    const float* U   = (const float*)d_in[2];   // (M,D+1,B) f32

    float* out  = (float*)d_out;                // writes (N,D) then loss scalar
    float* loss = out + (out_size - 1);

    cudaMemsetAsync(loss, 0, sizeof(float));    // only the loss scalar needs zeroing
    k_norm  <<<Mm, 256>>>(U);
    k_build <<<NA/256, 256>>>(idx);
    k_writes<<<Mm*S1, 256>>>(h, U);
    k_reduce<<<(Nn*Dd/8)/256, 256>>>(out);      // 2048 blocks, 2 quads/thread
    k_recon <<<Mm*S2, 256>>>(h, U, out, loss);
}

// round 11
// speedup vs baseline: 1.0689x; 1.0395x over previous
#include <cuda_runtime.h>
#include <cuda_bf16.h>
#include <cstdint>

// Problem constants
#define Nn   8192
#define Kk   4
#define Bb   16
#define Dd   512
#define Mm   64
#define DP1  513
#define CAP  1024
#define NA   (Nn*Kk)   // 32768 assignments

// Scratch (device globals — no allocation allowed)
__device__ float g_inv[Mm*Bb];            // 1/col-norm per (expert, b)
__device__ int   g_count[Mm];
__device__ int   g_list[Mm*CAP];          // assignment ids grouped by expert
__device__ float g_part[(size_t)NA*Dd];   // per-assignment partial writes (64MB)

typedef unsigned long long ull;

// ---- packed f32x2 helpers (sm_100+ PTX) ----
__device__ __forceinline__ ull pk2(float lo, float hi){
    ull v; asm("mov.b64 %0, {%1,%2};" : "=l"(v) : "f"(lo), "f"(hi)); return v;
}
__device__ __forceinline__ void unpk2(ull v, float& lo, float& hi){
    asm("mov.b64 {%0,%1}, %2;" : "=f"(lo), "=f"(hi) : "l"(v));
}
__device__ __forceinline__ void fma2(ull& d, ull a, ull b){
    asm("fma.rn.f32x2 %0, %1, %2, %0;" : "+l"(d) : "l"(a), "l"(b));
}
__device__ __forceinline__ void add2(ull& d, ull a){
    asm("add.rn.f32x2 %0, %0, %1;" : "+l"(d) : "l"(a));
}

// ---------------------------------------------------------------------------
// Kernel 1: column inverse norms (over all D+1 rows) + reset counters
// ---------------------------------------------------------------------------
__global__ void k_norm(const float* __restrict__ U){
    __shared__ float sm[256];
    const int m = blockIdx.x, t = threadIdx.x;
    const int b = t & 15, r0 = t >> 4;
    const float* Um = U + (size_t)m * DP1 * Bb;
    float s = 0.f;
    for (int d = r0; d < DP1; d += 16){
        float v = Um[d*Bb + b];
        s += v*v;
    }
    sm[t] = s;
    __syncthreads();
    if (t < 16){
        float tot = 0.f;
        #pragma unroll
        for (int i = 0; i < 16; i++) tot += sm[t + 16*i];
        float y = rsqrtf(tot);
        y = y * (1.5f - 0.5f*tot*y*y);   // one Newton step for accuracy
        g_inv[m*Bb + t] = y;
    }
    if (t == 0) g_count[m] = 0;
}

// ---------------------------------------------------------------------------
// Kernel 2: counting scatter of assignments into per-expert lists
// ---------------------------------------------------------------------------
__global__ void k_build(const int* __restrict__ idx){
    int a = blockIdx.x * blockDim.x + threadIdx.x;
    if (a < NA){
        int e = idx[a] & 63;
        int pos = atomicAdd(&g_count[e], 1);
        if (pos < CAP) g_list[e*CAP + pos] = a;
    }
}

// ---------------------------------------------------------------------------
// Kernel 3: writes pass, NO atomics. Thread owns d = 2t, 2t+1.
// S1=16 -> 1024 blocks, only ~32 serial matches per block (short chains).
// Vectorized float4 U prologue. Depth-2 pipeline on the h row.
// ---------------------------------------------------------------------------
#define S1 16
__global__ void __launch_bounds__(256) k_writes(const float* __restrict__ h,
                                                const float* __restrict__ U){
    const int e   = blockIdx.x >> 4;     // /S1
    const int sub = blockIdx.x & (S1-1);
    const int t   = threadIdx.x;
    const int d0  = 2*t;
    const float* Ue = U + (size_t)e * DP1 * Bb;

    // Pre-scaled expert rows for d0, d0+1 packed as f32x2 pairs (16 ull).
    // float4 loads: 8 LDG.128 per thread.
    ull u0[8], u1[8];
    {
        const float4* Uf = (const float4*)Ue;
        const float4* ivp = (const float4*)(g_inv + e*Bb);
        float4 iv0 = ivp[0], iv1 = ivp[1], iv2 = ivp[2], iv3 = ivp[3];
        float4 iv[4] = { iv0, iv1, iv2, iv3 };
        #pragma unroll
        for (int q = 0; q < 4; q++){
            float4 a4 = __ldg(Uf + (size_t)d0*4 + q);
            float4 b4 = __ldg(Uf + (size_t)(d0+1)*4 + q);
            u0[2*q]   = pk2(a4.x*iv[q].x, a4.y*iv[q].y);
            u0[2*q+1] = pk2(a4.z*iv[q].z, a4.w*iv[q].w);
            u1[2*q]   = pk2(b4.x*iv[q].x, b4.y*iv[q].y);
            u1[2*q+1] = pk2(b4.z*iv[q].z, b4.w*iv[q].w);
        }
    }

    int cnt = g_count[e]; if (cnt > CAP) cnt = CAP;
    const int s    = (cnt * sub) / S1;
    const int epos = (cnt * (sub+1)) / S1;
    if (s >= epos) return;

    int a = g_list[e*CAP + s];
    const float4* hp = (const float4*)(h + (size_t)a * Bb);
    float4 A0 = __ldg(hp+0), A1 = __ldg(hp+1), A2 = __ldg(hp+2), A3 = __ldg(hp+3);

    for (int i = s; i < epos; i++){
        ull hh[8] = { pk2(A0.x,A0.y), pk2(A0.z,A0.w), pk2(A1.x,A1.y), pk2(A1.z,A1.w),
                      pk2(A2.x,A2.y), pk2(A2.z,A2.w), pk2(A3.x,A3.y), pk2(A3.z,A3.w) };
        int an = a;
        if (i + 1 < epos) an = g_list[e*CAP + i + 1];
        const float4* hn = (const float4*)(h + (size_t)an * Bb);
        float4 B0 = __ldg(hn+0), B1 = __ldg(hn+1), B2 = __ldg(hn+2), B3 = __ldg(hn+3);

        ull acc0 = 0ull, acc1 = 0ull;
        #pragma unroll
        for (int p = 0; p < 8; p++){
            fma2(acc0, u0[p], hh[p]);
            fma2(acc1, u1[p], hh[p]);
        }
        float x, y;
        unpk2(acc0, x, y); float r0 = x + y;
        unpk2(acc1, x, y); float r1 = x + y;
        *(float2*)(g_part + (size_t)a * Dd + d0) = make_float2(r0, r1);

        a = an; A0 = B0; A1 = B1; A2 = B2; A3 = B3;
    }
}

// ---------------------------------------------------------------------------
// Kernel 3b: 4:1 reduce of partials into out. 2 independent quads per thread
// (8 outstanding LDG.128).
// ---------------------------------------------------------------------------
__global__ void __launch_bounds__(256) k_reduce(float* __restrict__ out){
    const int half = Nn*Dd/8;                        // 524288 quad-slots per half
    int i1 = blockIdx.x * 256 + threadIdx.x;
    int i2 = i1 + half;
    const int n1 = i1 >> 7, q1 = i1 & 127;
    const int n2 = i2 >> 7, q2 = i2 & 127;
    const float4* p1 = (const float4*)(g_part + (size_t)n1 * 4 * Dd);
    const float4* p2 = (const float4*)(g_part + (size_t)n2 * 4 * Dd);
    float4 a = __ldg(p1 + q1),       b = __ldg(p1 + q1 + 128);
    float4 c = __ldg(p1 + q1 + 256), d = __ldg(p1 + q1 + 384);
    float4 e = __ldg(p2 + q2),       f = __ldg(p2 + q2 + 128);
    float4 g = __ldg(p2 + q2 + 256), k = __ldg(p2 + q2 + 384);
    ((float4*)out)[i1] = make_float4(a.x+b.x+c.x+d.x, a.y+b.y+c.y+d.y,
                                     a.z+b.z+c.z+d.z, a.w+b.w+c.w+d.w);
    ((float4*)out)[i2] = make_float4(e.x+f.x+g.x+k.x, e.y+f.y+g.y+k.y,
                                     e.z+f.z+g.z+k.z, e.w+f.w+g.w+k.w);
}

// ---------------------------------------------------------------------------
// Kernel 4: recon + loss — PROVEN round-2 version (39us measured), S2=4.
// Un in SMEM (row pad 20 floats -> conflict-free LDS.128), one warp handles
// 4 matches, full butterfly reduce, atomic loss.
// ---------------------------------------------------------------------------
#define S2 4
__global__ void __launch_bounds__(256,2) k_recon(const float* __restrict__ h,
                                                 const float* __restrict__ U,
                                                 const float* __restrict__ w,
                                                 float* __restrict__ loss){
    __shared__ __align__(16) float Us[Dd*20];
    __shared__ float wred[8];
    const int e   = blockIdx.x >> 2;     // /S2
    const int sub = blockIdx.x & (S2-1);
    const float* Ue = U + (size_t)e * DP1 * Bb;

    // cooperative load + normalize into padded smem
    for (int i = threadIdx.x; i < Dd*Bb; i += 256){
        int d = i >> 4, b = i & 15;
        Us[d*20 + b] = Ue[i] * g_inv[e*Bb + b];
    }
    __syncthreads();

    int cnt = g_count[e]; if (cnt > CAP) cnt = CAP;
    const int s    = (cnt * sub) / S2;
    const int epos = (cnt * (sub+1)) / S2;
    const int lane = threadIdx.x & 31;
    const int wid  = threadIdx.x >> 5;

    float lsum = 0.f;

    for (int g0 = s + wid*4; g0 < epos; g0 += 8*4){
        int a_[4]; float vm[4];
        #pragma unroll
        for (int mi = 0; mi < 4; mi++){
            int gi = g0 + mi;
            bool v = gi < epos;
            a_[mi] = g_list[e*CAP + (v ? gi : (epos-1))];
            vm[mi] = v ? 1.f : 0.f;
        }
        const float* w0 = w + (size_t)(a_[0] >> 2) * Dd;
        const float* w1 = w + (size_t)(a_[1] >> 2) * Dd;
        const float* w2 = w + (size_t)(a_[2] >> 2) * Dd;
        const float* w3 = w + (size_t)(a_[3] >> 2) * Dd;

        ull r2[4][8];
        #pragma unroll
        for (int m = 0; m < 4; m++)
            #pragma unroll
            for (int p = 0; p < 8; p++) r2[m][p] = 0ull;

        for (int j = 0; j < 16; j++){
            const int d = lane + 32*j;
            float wv0 = __ldg(w0 + d), wv1 = __ldg(w1 + d);
            float wv2 = __ldg(w2 + d), wv3 = __ldg(w3 + d);
            ull ww0 = pk2(wv0, wv0), ww1 = pk2(wv1, wv1);
            ull ww2 = pk2(wv2, wv2), ww3 = pk2(wv3, wv3);
            const float4* row = (const float4*)&Us[d*20];
            #pragma unroll
            for (int bq = 0; bq < 4; bq++){
                float4 u = row[bq];
                ull uL = pk2(u.x, u.y), uH = pk2(u.z, u.w);
                fma2(r2[0][2*bq], ww0, uL); fma2(r2[0][2*bq+1], ww0, uH);
                fma2(r2[1][2*bq], ww1, uL); fma2(r2[1][2*bq+1], ww1, uH);
                fma2(r2[2][2*bq], ww2, uL); fma2(r2[2][2*bq+1], ww2, uH);
                fma2(r2[3][2*bq], ww3, uL); fma2(r2[3][2*bq+1], ww3, uH);
            }
        }

        // butterfly reduce across the 32 lanes (packed adds)
        #pragma unroll
        for (int ofs = 16; ofs > 0; ofs >>= 1){
            #pragma unroll
            for (int m = 0; m < 4; m++)
                #pragma unroll
                for (int p = 0; p < 8; p++){
                    ull o = __shfl_xor_sync(0xffffffffu, r2[m][p], ofs);
                    add2(r2[m][p], o);
                }
        }

        // loss terms (all lanes compute the same value; lane 0 accumulates)
        float tot = 0.f;
        #pragma unroll
        for (int m = 0; m < 4; m++){
            const float4* hp = (const float4*)(h + (size_t)a_[m] * Bb);
            float4 hq0 = hp[0], hq1 = hp[1], hq2 = hp[2], hq3 = hp[3];
            float hv[16] = { hq0.x,hq0.y,hq0.z,hq0.w, hq1.x,hq1.y,hq1.z,hq1.w,
                             hq2.x,hq2.y,hq2.z,hq2.w, hq3.x,hq3.y,hq3.z,hq3.w };
            float tm = 0.f;
            #pragma unroll
            for (int p = 0; p < 8; p++){
                float rl, rh; unpk2(r2[m][p], rl, rh);
                float d0 = rl - hv[2*p];
                float d1 = rh - hv[2*p+1];
                tm += d0*d0 + d1*d1;
            }
            tot += vm[m] * tm;
        }
        if (lane == 0) lsum += tot;
    }

    if (lane == 0) wred[wid] = lsum;
    __syncthreads();
    if (threadIdx.x == 0){
        float sblk = 0.f;
        #pragma unroll
        for (int i = 0; i < 8; i++) sblk += wred[i];
        atomicAdd(loss, sblk * (1.0f / (float)(Nn*Kk*Bb)));
    }
}

// ---------------------------------------------------------------------------
extern "C" void kernel_launch(void* const* d_in, const int* in_sizes, int n_in,
                              void* d_out, int out_size){
    const float* h   = (const float*)d_in[0];   // (N,K,B) f32
    const int*   idx = (const int*)  d_in[1];   // (N,K) i32
    const float* U   = (const float*)d_in[2];   // (M,D+1,B) f32

    float* out  = (float*)d_out;                // writes (N,D) then loss scalar
    float* loss = out + (out_size - 1);

    cudaMemsetAsync(loss, 0, sizeof(float));    // only the loss scalar needs zeroing
    k_norm  <<<Mm, 256>>>(U);
    k_build <<<NA/256, 256>>>(idx);
    k_writes<<<Mm*S1, 256>>>(h, U);
    k_reduce<<<(Nn*Dd/8)/256, 256>>>(out);      // 2048 blocks, 2 quads/thread
    k_recon <<<Mm*S2, 256>>>(h, U, out, loss);
}

// round 12
// speedup vs baseline: 1.3897x; 1.3002x over previous
#include <cuda_runtime.h>
#include <cuda_bf16.h>
#include <cstdint>

// Problem constants
#define Nn   8192
#define Kk   4
#define Bb   16
#define Dd   512
#define Mm   64
#define DP1  513
#define CAP  1024
#define NA   (Nn*Kk)   // 32768 assignments
#define CPAD 32        // counter padding: one 128B line per expert counter

// Scratch (device globals — no allocation allowed)
__device__ float g_inv[Mm*Bb];        // 1/col-norm per (expert, b)
__device__ int   g_cnt[Mm*CPAD];      // padded per-expert counters
__device__ int   g_list[Mm*CAP];      // assignment ids grouped by expert

typedef unsigned long long ull;

// ---- packed f32x2 helpers (sm_100+ PTX) ----
__device__ __forceinline__ ull pk2(float lo, float hi){
    ull v; asm("mov.b64 %0, {%1,%2};" : "=l"(v) : "f"(lo), "f"(hi)); return v;
}
__device__ __forceinline__ void unpk2(ull v, float& lo, float& hi){
    asm("mov.b64 {%0,%1}, %2;" : "=f"(lo), "=f"(hi) : "l"(v));
}
__device__ __forceinline__ void fma2(ull& d, ull a, ull b){
    asm("fma.rn.f32x2 %0, %1, %2, %0;" : "+l"(d) : "l"(a), "l"(b));
}
__device__ __forceinline__ void add2(ull& d, ull a){
    asm("add.rn.f32x2 %0, %0, %1;" : "+l"(d) : "l"(a));
}

// ---------------------------------------------------------------------------
// Kernel 1: column inverse norms (over all D+1 rows) + reset padded counters
// ---------------------------------------------------------------------------
__global__ void k_norm(const float* __restrict__ U){
    __shared__ float sm[256];
    const int m = blockIdx.x, t = threadIdx.x;
    const int b = t & 15, r0 = t >> 4;
    const float* Um = U + (size_t)m * DP1 * Bb;
    float s = 0.f;
    for (int d = r0; d < DP1; d += 16){
        float v = Um[d*Bb + b];
        s += v*v;
    }
    sm[t] = s;
    __syncthreads();
    if (t < 16){
        float tot = 0.f;
        #pragma unroll
        for (int i = 0; i < 16; i++) tot += sm[t + 16*i];
        float y = rsqrtf(tot);
        y = y * (1.5f - 0.5f*tot*y*y);   // one Newton step for accuracy
        g_inv[m*Bb + t] = y;
    }
    if (t == 0) g_cnt[m*CPAD] = 0;
}

// ---------------------------------------------------------------------------
// Kernel 2: counting scatter; padded counters -> 64 LTS slices in parallel
// ---------------------------------------------------------------------------
__global__ void k_build(const int* __restrict__ idx){
    int a = blockIdx.x * blockDim.x + threadIdx.x;
    if (a < NA){
        int e = idx[a] & 63;
        int pos = atomicAdd(&g_cnt[e*CPAD], 1);
        if (pos < CAP) g_list[e*CAP + pos] = a;
    }
}

// ---------------------------------------------------------------------------
// Kernel 3: writes pass (PROVEN R2 atomic body) + depth-2 h-row prefetch.
// Thread owns d=t and d=t+256; per match: 16 f32x2 FMAs + 2 scalar REDs.
// ---------------------------------------------------------------------------
#define S1 8
__global__ void __launch_bounds__(256) k_writes(const float* __restrict__ h,
                                                const float* __restrict__ U,
                                                float* __restrict__ out){
    const int e   = blockIdx.x >> 3;     // /S1
    const int sub = blockIdx.x & (S1-1);
    const int t   = threadIdx.x;
    const float* Ue = U + (size_t)e * DP1 * Bb;

    // Pre-scaled expert rows for d0=t, d1=t+256, packed as f32x2 pairs
    ull u0[8], u1[8];
    #pragma unroll
    for (int p = 0; p < 8; p++){
        float i0 = g_inv[e*Bb + 2*p];
        float i1 = g_inv[e*Bb + 2*p + 1];
        u0[p] = pk2(Ue[(size_t)t*Bb + 2*p]*i0,         Ue[(size_t)t*Bb + 2*p + 1]*i1);
        u1[p] = pk2(Ue[(size_t)(t+256)*Bb + 2*p]*i0,   Ue[(size_t)(t+256)*Bb + 2*p + 1]*i1);
    }

    int cnt = g_cnt[e*CPAD]; if (cnt > CAP) cnt = CAP;
    const int s    = (cnt * sub) / S1;
    const int epos = (cnt * (sub+1)) / S1;
    if (s >= epos) return;

    int a = g_list[e*CAP + s];
    const float4* hp = (const float4*)(h + (size_t)a * Bb);
    float4 A0 = __ldg(hp+0), A1 = __ldg(hp+1), A2 = __ldg(hp+2), A3 = __ldg(hp+3);

    for (int i = s; i < epos; i++){
        ull hh[8] = { pk2(A0.x,A0.y), pk2(A0.z,A0.w), pk2(A1.x,A1.y), pk2(A1.z,A1.w),
                      pk2(A2.x,A2.y), pk2(A2.z,A2.w), pk2(A3.x,A3.y), pk2(A3.z,A3.w) };
        int an = a;
        if (i + 1 < epos) an = g_list[e*CAP + i + 1];
        const float4* hn = (const float4*)(h + (size_t)an * Bb);
        float4 B0 = __ldg(hn+0), B1 = __ldg(hn+1), B2 = __ldg(hn+2), B3 = __ldg(hn+3);

        ull acc0 = 0ull, acc1 = 0ull;
        #pragma unroll
        for (int p = 0; p < 8; p++){
            fma2(acc0, u0[p], hh[p]);
            fma2(acc1, u1[p], hh[p]);
        }
        float x, y;
        unpk2(acc0, x, y); float r0 = x + y;
        unpk2(acc1, x, y); float r1 = x + y;
        float* w = out + (size_t)(a >> 2) * Dd;
        atomicAdd(w + t,       r0);   // RED (no return)
        atomicAdd(w + t + 256, r1);

        a = an; A0 = B0; A1 = B1; A2 = B2; A3 = B3;
    }
}

// ---------------------------------------------------------------------------
// Kernel 4: recon + loss — PROVEN R2 version (39us measured), S2=4.
// Un in SMEM (row pad 20 floats), one warp handles 4 matches, full
// butterfly reduce, atomic loss.
// ---------------------------------------------------------------------------
#define S2 4
__global__ void __launch_bounds__(256,2) k_recon(const float* __restrict__ h,
                                                 const float* __restrict__ U,
                                                 const float* __restrict__ w,
                                                 float* __restrict__ loss){
    __shared__ __align__(16) float Us[Dd*20];
    __shared__ float wred[8];
    const int e   = blockIdx.x >> 2;     // /S2
    const int sub = blockIdx.x & (S2-1);
    const float* Ue = U + (size_t)e * DP1 * Bb;

    // cooperative load + normalize into padded smem
    for (int i = threadIdx.x; i < Dd*Bb; i += 256){
        int d = i >> 4, b = i & 15;
        Us[d*20 + b] = Ue[i] * g_inv[e*Bb + b];
    }
    __syncthreads();

    int cnt = g_cnt[e*CPAD]; if (cnt > CAP) cnt = CAP;
    const int s    = (cnt * sub) / S2;
    const int epos = (cnt * (sub+1)) / S2;
    const int lane = threadIdx.x & 31;
    const int wid  = threadIdx.x >> 5;

    float lsum = 0.f;

    for (int g0 = s + wid*4; g0 < epos; g0 += 8*4){
        int a_[4]; float vm[4];
        #pragma unroll
        for (int mi = 0; mi < 4; mi++){
            int gi = g0 + mi;
            bool v = gi < epos;
            a_[mi] = g_list[e*CAP + (v ? gi : (epos-1))];
            vm[mi] = v ? 1.f : 0.f;
        }
        const float* w0 = w + (size_t)(a_[0] >> 2) * Dd;
        const float* w1 = w + (size_t)(a_[1] >> 2) * Dd;
        const float* w2 = w + (size_t)(a_[2] >> 2) * Dd;
        const float* w3 = w + (size_t)(a_[3] >> 2) * Dd;

        ull r2[4][8];
        #pragma unroll
        for (int m = 0; m < 4; m++)
            #pragma unroll
            for (int p = 0; p < 8; p++) r2[m][p] = 0ull;

        for (int j = 0; j < 16; j++){
            const int d = lane + 32*j;
            float wv0 = __ldg(w0 + d), wv1 = __ldg(w1 + d);
            float wv2 = __ldg(w2 + d), wv3 = __ldg(w3 + d);
            ull ww0 = pk2(wv0, wv0), ww1 = pk2(wv1, wv1);
            ull ww2 = pk2(wv2, wv2), ww3 = pk2(wv3, wv3);
            const float4* row = (const float4*)&Us[d*20];
            #pragma unroll
            for (int bq = 0; bq < 4; bq++){
                float4 u = row[bq];
                ull uL = pk2(u.x, u.y), uH = pk2(u.z, u.w);
                fma2(r2[0][2*bq], ww0, uL); fma2(r2[0][2*bq+1], ww0, uH);
                fma2(r2[1][2*bq], ww1, uL); fma2(r2[1][2*bq+1], ww1, uH);
                fma2(r2[2][2*bq], ww2, uL); fma2(r2[2][2*bq+1], ww2, uH);
                fma2(r2[3][2*bq], ww3, uL); fma2(r2[3][2*bq+1], ww3, uH);
            }
        }

        // butterfly reduce across the 32 lanes (packed adds)
        #pragma unroll
        for (int ofs = 16; ofs > 0; ofs >>= 1){
            #pragma unroll
            for (int m = 0; m < 4; m++)
                #pragma unroll
                for (int p = 0; p < 8; p++){
                    ull o = __shfl_xor_sync(0xffffffffu, r2[m][p], ofs);
                    add2(r2[m][p], o);
                }
        }

        // loss terms (all lanes compute the same value; lane 0 accumulates)
        float tot = 0.f;
        #pragma unroll
        for (int m = 0; m < 4; m++){
            const float4* hp = (const float4*)(h + (size_t)a_[m] * Bb);
            float4 hq0 = hp[0], hq1 = hp[1], hq2 = hp[2], hq3 = hp[3];
            float hv[16] = { hq0.x,hq0.y,hq0.z,hq0.w, hq1.x,hq1.y,hq1.z,hq1.w,
                             hq2.x,hq2.y,hq2.z,hq2.w, hq3.x,hq3.y,hq3.z,hq3.w };
            float tm = 0.f;
            #pragma unroll
            for (int p = 0; p < 8; p++){
                float rl, rh; unpk2(r2[m][p], rl, rh);
                float d0 = rl - hv[2*p];
                float d1 = rh - hv[2*p+1];
                tm += d0*d0 + d1*d1;
            }
            tot += vm[m] * tm;
        }
        if (lane == 0) lsum += tot;
    }

    if (lane == 0) wred[wid] = lsum;
    __syncthreads();
    if (threadIdx.x == 0){
        float sblk = 0.f;
        #pragma unroll
        for (int i = 0; i < 8; i++) sblk += wred[i];
        atomicAdd(loss, sblk * (1.0f / (float)(Nn*Kk*Bb)));
    }
}

// ---------------------------------------------------------------------------
extern "C" void kernel_launch(void* const* d_in, const int* in_sizes, int n_in,
                              void* d_out, int out_size){
    const float* h   = (const float*)d_in[0];   // (N,K,B) f32
    const int*   idx = (const int*)  d_in[1];   // (N,K) i32
    const float* U   = (const float*)d_in[2];   // (M,D+1,B) f32

    float* out  = (float*)d_out;                // writes (N,D) then loss scalar
    float* loss = out + (out_size - 1);

    cudaMemsetAsync(d_out, 0, (size_t)out_size * sizeof(float));  // atomic targets need zeros
    k_norm  <<<Mm, 256>>>(U);
    k_build <<<NA/256, 256>>>(idx);
    k_writes<<<Mm*S1, 256>>>(h, U, out);
    k_recon <<<Mm*S2, 256>>>(h, U, out, loss);
}

// round 15
// speedup vs baseline: 1.5933x; 1.1465x over previous
#include <cuda_runtime.h>
#include <cuda_bf16.h>
#include <cstdint>

// Problem constants
#define Nn   8192
#define Kk   4
#define Bb   16
#define Dd   512
#define Mm   64
#define DP1  513
#define CAP  1024
#define NA   (Nn*Kk)   // 32768 assignments
#define CPAD 32        // counter padding: one 128B line per expert counter

// Scratch (device globals — no allocation allowed)
__device__ float g_inv[Mm*Bb];        // 1/col-norm per (expert, b)
__device__ int   g_cnt[Mm*CPAD];      // padded per-expert counters
__device__ int   g_list[Mm*CAP];      // assignment ids grouped by expert

typedef unsigned long long ull;

// ---- packed f32x2 helpers (sm_100+ PTX) ----
__device__ __forceinline__ ull pk2(float lo, float hi){
    ull v; asm("mov.b64 %0, {%1,%2};" : "=l"(v) : "f"(lo), "f"(hi)); return v;
}
__device__ __forceinline__ void unpk2(ull v, float& lo, float& hi){
    asm("mov.b64 {%0,%1}, %2;" : "=f"(lo), "=f"(hi) : "l"(v));
}
__device__ __forceinline__ void fma2(ull& d, ull a, ull b){
    asm("fma.rn.f32x2 %0, %1, %2, %0;" : "+l"(d) : "l"(a), "l"(b));
}
__device__ __forceinline__ void add2(ull& d, ull a){
    asm("add.rn.f32x2 %0, %0, %1;" : "+l"(d) : "l"(a));
}

// ---------------------------------------------------------------------------
// Kernel 1: column inverse norms (over all D+1 rows) + reset padded counters
// ---------------------------------------------------------------------------
__global__ void k_norm(const float* __restrict__ U){
    __shared__ float sm[256];
    const int m = blockIdx.x, t = threadIdx.x;
    const int b = t & 15, r0 = t >> 4;
    const float* Um = U + (size_t)m * DP1 * Bb;
    float s = 0.f;
    for (int d = r0; d < DP1; d += 16){
        float v = Um[d*Bb + b];
        s += v*v;
    }
    sm[t] = s;
    __syncthreads();
    if (t < 16){
        float tot = 0.f;
        #pragma unroll
        for (int i = 0; i < 16; i++) tot += sm[t + 16*i];
        float y = rsqrtf(tot);
        y = y * (1.5f - 0.5f*tot*y*y);   // one Newton step for accuracy
        g_inv[m*Bb + t] = y;
    }
    if (t == 0) g_cnt[m*CPAD] = 0;
}

// ---------------------------------------------------------------------------
// Kernel 2: counting scatter; padded counters -> 64 LTS slices in parallel
// ---------------------------------------------------------------------------
__global__ void k_build(const int* __restrict__ idx){
    int a = blockIdx.x * blockDim.x + threadIdx.x;
    if (a < NA){
        int e = idx[a] & 63;
        int pos = atomicAdd(&g_cnt[e*CPAD], 1);
        if (pos < CAP) g_list[e*CAP + pos] = a;
    }
}

// ---------------------------------------------------------------------------
// Kernel 3: writes pass (PROVEN R12: atomic body + depth-2 h-row prefetch).
// Thread owns d=t and d=t+256; per match: 16 f32x2 FMAs + 2 scalar REDs.
// ---------------------------------------------------------------------------
#define S1 8
__global__ void __launch_bounds__(256) k_writes(const float* __restrict__ h,
                                                const float* __restrict__ U,
                                                float* __restrict__ out){
    const int e   = blockIdx.x >> 3;     // /S1
    const int sub = blockIdx.x & (S1-1);
    const int t   = threadIdx.x;
    const float* Ue = U + (size_t)e * DP1 * Bb;

    // Pre-scaled expert rows for d0=t, d1=t+256, packed as f32x2 pairs
    ull u0[8], u1[8];
    #pragma unroll
    for (int p = 0; p < 8; p++){
        float i0 = g_inv[e*Bb + 2*p];
        float i1 = g_inv[e*Bb + 2*p + 1];
        u0[p] = pk2(Ue[(size_t)t*Bb + 2*p]*i0,         Ue[(size_t)t*Bb + 2*p + 1]*i1);
        u1[p] = pk2(Ue[(size_t)(t+256)*Bb + 2*p]*i0,   Ue[(size_t)(t+256)*Bb + 2*p + 1]*i1);
    }

    int cnt = g_cnt[e*CPAD]; if (cnt > CAP) cnt = CAP;
    const int s    = (cnt * sub) / S1;
    const int epos = (cnt * (sub+1)) / S1;
    if (s >= epos) return;

    int a = g_list[e*CAP + s];
    const float4* hp = (const float4*)(h + (size_t)a * Bb);
    float4 A0 = __ldg(hp+0), A1 = __ldg(hp+1), A2 = __ldg(hp+2), A3 = __ldg(hp+3);

    for (int i = s; i < epos; i++){
        ull hh[8] = { pk2(A0.x,A0.y), pk2(A0.z,A0.w), pk2(A1.x,A1.y), pk2(A1.z,A1.w),
                      pk2(A2.x,A2.y), pk2(A2.z,A2.w), pk2(A3.x,A3.y), pk2(A3.z,A3.w) };
        int an = a;
        if (i + 1 < epos) an = g_list[e*CAP + i + 1];
        const float4* hn = (const float4*)(h + (size_t)an * Bb);
        float4 B0 = __ldg(hn+0), B1 = __ldg(hn+1), B2 = __ldg(hn+2), B3 = __ldg(hn+3);

        ull acc0 = 0ull, acc1 = 0ull;
        #pragma unroll
        for (int p = 0; p < 8; p++){
            fma2(acc0, u0[p], hh[p]);
            fma2(acc1, u1[p], hh[p]);
        }
        float x, y;
        unpk2(acc0, x, y); float r0 = x + y;
        unpk2(acc1, x, y); float r1 = x + y;
        float* w = out + (size_t)(a >> 2) * Dd;
        atomicAdd(w + t,       r0);   // RED (no return)
        atomicAdd(w + t + 256, r1);

        a = an; A0 = B0; A1 = B1; A2 = B2; A3 = B3;
    }
}

// ---------------------------------------------------------------------------
// Kernel 4: recon + loss. R12 k-loop unchanged; the all-lanes butterfly
// (320 SHFL + 160 add2 per group) is replaced by a single-shuffle
// register-halving tree (31 SHFL.64 + 31 add2): lane L ends holding the
// fully-reduced value v=L (m = L>>3, b-pair = L&7). Loss becomes per-lane;
// the cross-lane loss reduce moves out of the group loop.
// ---------------------------------------------------------------------------
#define S2 4
__global__ void __launch_bounds__(256,2) k_recon(const float* __restrict__ h,
                                                 const float* __restrict__ U,
                                                 const float* __restrict__ w,
                                                 float* __restrict__ loss){
    __shared__ __align__(16) float Us[Dd*20];
    __shared__ float wred[8];
    const int e   = blockIdx.x >> 2;     // /S2
    const int sub = blockIdx.x & (S2-1);
    const float* Ue = U + (size_t)e * DP1 * Bb;

    // cooperative load + normalize into padded smem
    for (int i = threadIdx.x; i < Dd*Bb; i += 256){
        int d = i >> 4, b = i & 15;
        Us[d*20 + b] = Ue[i] * g_inv[e*Bb + b];
    }
    __syncthreads();

    int cnt = g_cnt[e*CPAD]; if (cnt > CAP) cnt = CAP;
    const int s    = (cnt * sub) / S2;
    const int epos = (cnt * (sub+1)) / S2;
    const int lane = threadIdx.x & 31;
    const int wid  = threadIdx.x >> 5;

    float lsum = 0.f;   // per-lane partial loss

    for (int g0 = s + wid*4; g0 < epos; g0 += 8*4){
        int a_[4]; float vm[4];
        #pragma unroll
        for (int mi = 0; mi < 4; mi++){
            int gi = g0 + mi;
            bool v = gi < epos;
            a_[mi] = g_list[e*CAP + (v ? gi : (epos-1))];
            vm[mi] = v ? 1.f : 0.f;
        }
        const float* w0 = w + (size_t)(a_[0] >> 2) * Dd;
        const float* w1 = w + (size_t)(a_[1] >> 2) * Dd;
        const float* w2 = w + (size_t)(a_[2] >> 2) * Dd;
        const float* w3 = w + (size_t)(a_[3] >> 2) * Dd;

        ull r2[32];   // flattened: v = m*8 + p
        #pragma unroll
        for (int p = 0; p < 32; p++) r2[p] = 0ull;

        for (int j = 0; j < 16; j++){
            const int d = lane + 32*j;
            float wv0 = __ldg(w0 + d), wv1 = __ldg(w1 + d);
            float wv2 = __ldg(w2 + d), wv3 = __ldg(w3 + d);
            ull ww0 = pk2(wv0, wv0), ww1 = pk2(wv1, wv1);
            ull ww2 = pk2(wv2, wv2), ww3 = pk2(wv3, wv3);
            const float4* row = (const float4*)&Us[d*20];
            #pragma unroll
            for (int bq = 0; bq < 4; bq++){
                float4 u = row[bq];
                ull uL = pk2(u.x, u.y), uH = pk2(u.z, u.w);
                fma2(r2[2*bq],      ww0, uL); fma2(r2[2*bq+1],      ww0, uH);
                fma2(r2[8+2*bq],    ww1, uL); fma2(r2[8+2*bq+1],    ww1, uH);
                fma2(r2[16+2*bq],   ww2, uL); fma2(r2[16+2*bq+1],   ww2, uH);
                fma2(r2[24+2*bq],   ww3, uL); fma2(r2[24+2*bq+1],   ww3, uH);
            }
        }

        // register-halving tree: 32 ull/lane -> lane L holds full sum of v=L.
        // One shuffle per surviving value: send what the partner needs.
        #pragma unroll
        for (int o = 16; o >= 1; o >>= 1){
            const bool hb = (lane & o) != 0;
            #pragma unroll
            for (int i = 0; i < o; i++){
                ull send = hb ? r2[i]     : r2[i + o];
                ull keep = hb ? r2[i + o] : r2[i];
                ull recv = __shfl_xor_sync(0xffffffffu, send, o);
                add2(keep, recv);
                r2[i] = keep;
            }
        }

        // per-lane loss: lane owns (m = lane>>3, b = 2*(lane&7), +1)
        int   am  = a_[0]; float vmm = vm[0];
        if (lane >= 8)  { am = a_[1]; vmm = vm[1]; }
        if (lane >= 16) { am = a_[2]; vmm = vm[2]; }
        if (lane >= 24) { am = a_[3]; vmm = vm[3]; }
        const float2 hv = *(const float2*)(h + (size_t)am * Bb + 2*(lane & 7));
        float rl, rh; unpk2(r2[0], rl, rh);
        float e0 = rl - hv.x, e1 = rh - hv.y;
        lsum += vmm * (e0*e0 + e1*e1);
    }

    // one warp-wide loss reduce (outside the group loop)
    #pragma unroll
    for (int ofs = 16; ofs > 0; ofs >>= 1)
        lsum += __shfl_xor_sync(0xffffffffu, lsum, ofs);
    if (lane == 0) wred[wid] = lsum;
    __syncthreads();
    if (threadIdx.x == 0){
        float sblk = 0.f;
        #pragma unroll
        for (int i = 0; i < 8; i++) sblk += wred[i];
        atomicAdd(loss, sblk * (1.0f / (float)(Nn*Kk*Bb)));
    }
}

// ---------------------------------------------------------------------------
extern "C" void kernel_launch(void* const* d_in, const int* in_sizes, int n_in,
                              void* d_out, int out_size){
    const float* h   = (const float*)d_in[0];   // (N,K,B) f32
    const int*   idx = (const int*)  d_in[1];   // (N,K) i32
    const float* U   = (const float*)d_in[2];   // (M,D+1,B) f32

    float* out  = (float*)d_out;                // writes (N,D) then loss scalar
    float* loss = out + (out_size - 1);

    cudaMemsetAsync(d_out, 0, (size_t)out_size * sizeof(float));  // atomic targets need zeros
    k_norm  <<<Mm, 256>>>(U);
    k_build <<<NA/256, 256>>>(idx);
    k_writes<<<Mm*S1, 256>>>(h, U, out);
    k_recon <<<Mm*S2, 256>>>(h, U, out, loss);
}